// round 1
// baseline (speedup 1.0000x reference)
#include <cuda_runtime.h>
#include <cstdint>
#include <cstddef>

// Problem constants
#define T_STEPS 784
#define NBATCH  128
#define HID     512
#define OUTC    10
#define DECAY   0.2f
#define THRESH  0.5f

// Scratch: S1, S2 spike sequences and one shared GEMM-output buffer C.
// Each is [T][N][H] fp32 = 784*128*512 floats = ~205.5 MB. Static __device__
// globals (allocation inside kernel_launch is forbidden).
#define SEQ_ELEMS ((size_t)T_STEPS * NBATCH * HID)
__device__ float g_S1[SEQ_ELEMS];
__device__ float g_S2[SEQ_ELEMS];
__device__ float g_C [SEQ_ELEMS];

// ---------------------------------------------------------------------------
// Kernel 1: layer-1 recurrence. One thread per (n, i). Writes S1 and fr1.
// inp contribution per step is x[n,t] * W1[i] + b1[i].
// ---------------------------------------------------------------------------
__global__ void layer1_kernel(const float* __restrict__ x,
                              const float* __restrict__ W1,
                              const float* __restrict__ b1,
                              const float* __restrict__ mask1,
                              float* __restrict__ fr1)
{
    const int n = blockIdx.x;     // 0..127
    const int i = threadIdx.x;    // 0..511
    const float w = W1[i];
    const float b = b1[i];
    const float* __restrict__ xr = x + (size_t)n * T_STEPS;
    const float* __restrict__ mr = mask1 + (size_t)i * T_STEPS;

    float mem = 0.f, spike = 0.f, ss = 0.f;
    for (int t = 0; t < T_STEPS; ++t) {
        const float m_t = mr[t];
        const float x_t = xr[t];
        const float new_mem = mem * DECAY * (1.f - spike) + x_t * w + b;
        if (m_t != 0.f) mem = new_mem;
        const float spk = (mem > THRESH) ? m_t : 0.f;   // m_t is exactly 1.0 when on
        g_S1[((size_t)t * NBATCH + n) * HID + i] = spk;
        ss += spk;
        spike = spk;
    }
    fr1[n * HID + i] = ss * (1.f / (float)T_STEPS);
}

// ---------------------------------------------------------------------------
// Kernel: fp32 SGEMM  C[m][j] = sum_k A[m][k] * B[j][k]
// A: [M=100352, K=512] (spike sequence), B: [512, 512] weights (row-major,
// K-contiguous). Block tile 128x128, BK=8, 256 threads, 8x8 per thread.
// which: 0 -> A=g_S1, 1 -> A=g_S2; C always g_C.
// ---------------------------------------------------------------------------
#define BM 128
#define BN 128
#define BKK 8

__global__ void __launch_bounds__(256, 2)
sgemm_nt(const float* __restrict__ B, int which)
{
    const float* __restrict__ A = (which == 0) ? g_S1 : g_S2;
    float* __restrict__ C = g_C;

    __shared__ float As[BKK][BM];
    __shared__ float Bs[BKK][BN];

    const int bm = blockIdx.x;         // 0..783
    const int bn = blockIdx.y;         // 0..3
    const int tid = threadIdx.x;

    const int lr = tid >> 1;           // 0..127
    const int lc = (tid & 1) * 4;      // 0 or 4
    const float* Ab = A + ((size_t)bm * BM + lr) * 512 + lc;
    const float* Bb = B + ((size_t)bn * BN + lr) * 512 + lc;

    const int row0 = (tid >> 4) * 8;   // 16 groups * 8 rows
    const int col0 = (tid & 15) * 8;   // 16 groups * 8 cols

    float acc[8][8];
#pragma unroll
    for (int u = 0; u < 8; ++u)
#pragma unroll
        for (int v = 0; v < 8; ++v) acc[u][v] = 0.f;

    for (int k0 = 0; k0 < 512; k0 += BKK) {
        const float4 a  = *(const float4*)(Ab + k0);
        const float4 bb = *(const float4*)(Bb + k0);
        __syncthreads();
        As[lc + 0][lr] = a.x;  As[lc + 1][lr] = a.y;
        As[lc + 2][lr] = a.z;  As[lc + 3][lr] = a.w;
        Bs[lc + 0][lr] = bb.x; Bs[lc + 1][lr] = bb.y;
        Bs[lc + 2][lr] = bb.z; Bs[lc + 3][lr] = bb.w;
        __syncthreads();
#pragma unroll
        for (int kk = 0; kk < BKK; ++kk) {
            float a0[8], b0[8];
#pragma unroll
            for (int u = 0; u < 8; ++u) { a0[u] = As[kk][row0 + u]; b0[u] = Bs[kk][col0 + u]; }
#pragma unroll
            for (int u = 0; u < 8; ++u)
#pragma unroll
                for (int v = 0; v < 8; ++v) acc[u][v] += a0[u] * b0[v];
        }
    }

    float* Cb = C + ((size_t)bm * BM + row0) * 512 + (size_t)bn * BN + col0;
#pragma unroll
    for (int u = 0; u < 8; ++u) {
        float4 s0 = make_float4(acc[u][0], acc[u][1], acc[u][2], acc[u][3]);
        float4 s1 = make_float4(acc[u][4], acc[u][5], acc[u][6], acc[u][7]);
        *(float4*)(Cb + (size_t)u * 512 + 0) = s0;
        *(float4*)(Cb + (size_t)u * 512 + 4) = s1;
    }
}

// ---------------------------------------------------------------------------
// Kernel: layer-2/3 recurrence. One thread per (n, j). Reads g_C (which holds
// S_prev @ W^T), updates membrane, writes spikes (layer 2 -> g_S2) and fr.
// layer: 2 -> store spikes to g_S2; 3 -> no spike store.
// ---------------------------------------------------------------------------
__global__ void layerR_kernel(const float* __restrict__ bvec,
                              const float* __restrict__ mask,
                              float* __restrict__ fr,
                              int layer)
{
    const int n = blockIdx.x;
    const int j = threadIdx.x;
    const float bj = bvec[j];
    const float* __restrict__ mr = mask + (size_t)j * T_STEPS;

    float mem = 0.f, spike = 0.f, ss = 0.f;
    for (int t = 0; t < T_STEPS; ++t) {
        const float m_t = mr[t];
        const float c = g_C[((size_t)t * NBATCH + n) * HID + j];
        const float new_mem = mem * DECAY * (1.f - spike) + c + bj;
        if (m_t != 0.f) mem = new_mem;
        const float spk = (mem > THRESH) ? m_t : 0.f;
        if (layer == 2) g_S2[((size_t)t * NBATCH + n) * HID + j] = spk;
        ss += spk;
        spike = spk;
    }
    fr[n * HID + j] = ss * (1.f / (float)T_STEPS);
}

// ---------------------------------------------------------------------------
// Kernel: final head.  outputs[n][oc] = fr3[n] . W4[oc] + b4[oc]
// (osum/T collapses to fr3 @ W4^T + b4 since b4 is added T times then /T).
// grid = 128 blocks (n), 320 threads = 10 warps (oc).
// ---------------------------------------------------------------------------
__global__ void head_kernel(const float* __restrict__ fr3,
                            const float* __restrict__ W4,
                            const float* __restrict__ b4,
                            float* __restrict__ outputs)
{
    const int n = blockIdx.x;
    const int warp = threadIdx.x >> 5;
    const int lane = threadIdx.x & 31;
    const float* __restrict__ f = fr3 + (size_t)n * HID;
    const float* __restrict__ w = W4 + (size_t)warp * HID;
    float s = 0.f;
    for (int j = lane; j < HID; j += 32) s += f[j] * w[j];
#pragma unroll
    for (int o = 16; o > 0; o >>= 1) s += __shfl_xor_sync(0xffffffffu, s, o);
    if (lane == 0) outputs[n * OUTC + warp] = s + b4[warp];
}

// ---------------------------------------------------------------------------
// Kernel: layer_fr[l] = mean(fr_l)  (fr blocks contiguous in d_out).
// Deterministic tree reduction, 3 blocks.
// ---------------------------------------------------------------------------
__global__ void lfr_kernel(const float* __restrict__ fr_all,
                           float* __restrict__ out3)
{
    const int l = blockIdx.x;
    const float* __restrict__ f = fr_all + (size_t)l * (NBATCH * HID);
    __shared__ float sh[256];
    float s = 0.f;
    for (int idx = threadIdx.x; idx < NBATCH * HID; idx += 256) s += f[idx];
    sh[threadIdx.x] = s;
    __syncthreads();
    for (int o = 128; o > 0; o >>= 1) {
        if (threadIdx.x < o) sh[threadIdx.x] += sh[threadIdx.x + o];
        __syncthreads();
    }
    if (threadIdx.x == 0) out3[l] = sh[0] * (1.f / (float)(NBATCH * HID));
}

// ---------------------------------------------------------------------------
// Launch. Inputs (metadata order):
// 0:x 1:W1 2:b1 3:W2 4:b2 5:W3 6:b3 7:W4 8:b4 9:mask1 10:mask2 11:mask3
// Output layout (flattened tuple): outputs[128*10], fr1[128*512],
// fr2[128*512], fr3[128*512], layer_fr[3]
// ---------------------------------------------------------------------------
extern "C" void kernel_launch(void* const* d_in, const int* in_sizes, int n_in,
                              void* d_out, int out_size)
{
    const float* x     = (const float*)d_in[0];
    const float* W1    = (const float*)d_in[1];
    const float* b1    = (const float*)d_in[2];
    const float* W2    = (const float*)d_in[3];
    const float* b2    = (const float*)d_in[4];
    const float* W3    = (const float*)d_in[5];
    const float* b3    = (const float*)d_in[6];
    const float* W4    = (const float*)d_in[7];
    const float* b4    = (const float*)d_in[8];
    const float* mask1 = (const float*)d_in[9];
    const float* mask2 = (const float*)d_in[10];
    const float* mask3 = (const float*)d_in[11];

    float* out     = (float*)d_out;
    float* outputs = out;                       // 1280
    float* fr1     = out + NBATCH * OUTC;       // 65536
    float* fr2     = fr1 + NBATCH * HID;
    float* fr3     = fr2 + NBATCH * HID;
    float* lfr     = fr3 + NBATCH * HID;        // 3

    dim3 gemm_grid(T_STEPS, 4);

    layer1_kernel<<<NBATCH, HID>>>(x, W1, b1, mask1, fr1);
    sgemm_nt<<<gemm_grid, 256>>>(W2, 0);
    layerR_kernel<<<NBATCH, HID>>>(b2, mask2, fr2, 2);
    sgemm_nt<<<gemm_grid, 256>>>(W3, 1);
    layerR_kernel<<<NBATCH, HID>>>(b3, mask3, fr3, 3);
    head_kernel<<<NBATCH, 320>>>(fr3, W4, b4, outputs);
    lfr_kernel<<<3, 256>>>(fr1, lfr);
}

// round 3
// speedup vs baseline: 2.6010x; 2.6010x over previous
#include <cuda_runtime.h>
#include <cuda_bf16.h>
#include <cstdint>
#include <cstddef>

// Problem constants
#define T_STEPS 784
#define NBATCH  128
#define HID     512
#define OUTC    10
#define DECAY   0.2f
#define THRESH  0.5f
#define KDIM    512

// GEMM tiling
#define BM 128
#define BN 128
#define BK 64
#define ROWB 144u              // smem bytes per row: 64 bf16 (128B) + 16B pad
#define TILEB (128u * ROWB)    // 18432 B
#define STAGEB (3u * TILEB)    // A + Wh + Wl per stage
#define GEMM_SMEM (2u * STAGEB)  // 110592 B double-buffered

#define SEQ_ELEMS ((size_t)T_STEPS * NBATCH * HID)
__device__ __nv_bfloat16 g_S1b[SEQ_ELEMS];   // layer-1 spikes [t][n][i] (exact 0/1)
__device__ __nv_bfloat16 g_S2b[SEQ_ELEMS];   // layer-2 spikes
__device__ float         g_C  [SEQ_ELEMS];   // GEMM output [t][n][j] fp32
__device__ __nv_bfloat16 g_W2h[HID*HID], g_W2l[HID*HID];
__device__ __nv_bfloat16 g_W3h[HID*HID], g_W3l[HID*HID];

// ---------------------------------------------------------------------------
// PTX helpers (sm_80-era: ldmatrix / mma.sync / cp.async — safe for sm_103)
// ---------------------------------------------------------------------------
__device__ __forceinline__ uint32_t smem_u32(const void* p){
    uint32_t a;
    asm("{ .reg .u64 t; cvta.to.shared.u64 t, %1; cvt.u32.u64 %0, t; }" : "=r"(a) : "l"(p));
    return a;
}
__device__ __forceinline__ void cp16(uint32_t saddr, const void* gaddr){
    asm volatile("cp.async.cg.shared.global [%0], [%1], 16;" :: "r"(saddr), "l"(gaddr));
}
__device__ __forceinline__ void ldsm4(uint32_t* r, uint32_t addr){
    asm volatile("ldmatrix.sync.aligned.m8n8.x4.shared.b16 {%0,%1,%2,%3}, [%4];"
        : "=r"(r[0]), "=r"(r[1]), "=r"(r[2]), "=r"(r[3]) : "r"(addr));
}
__device__ __forceinline__ void ldsm2(uint32_t* r, uint32_t addr){
    asm volatile("ldmatrix.sync.aligned.m8n8.x2.shared.b16 {%0,%1}, [%2];"
        : "=r"(r[0]), "=r"(r[1]) : "r"(addr));
}
__device__ __forceinline__ void mma_bf16(float* c, const uint32_t* a, const uint32_t* b){
    asm volatile(
        "mma.sync.aligned.m16n8k16.row.col.f32.bf16.bf16.f32 "
        "{%0,%1,%2,%3}, {%4,%5,%6,%7}, {%8,%9}, {%0,%1,%2,%3};"
        : "+f"(c[0]), "+f"(c[1]), "+f"(c[2]), "+f"(c[3])
        : "r"(a[0]), "r"(a[1]), "r"(a[2]), "r"(a[3]), "r"(b[0]), "r"(b[1]));
}

// ---------------------------------------------------------------------------
// Weight split: W -> hi(bf16) + lo(bf16); residual ~2^-16 |w|
// ---------------------------------------------------------------------------
__global__ void split_kernel(const float* __restrict__ W2, const float* __restrict__ W3){
    int idx = blockIdx.x * blockDim.x + threadIdx.x;
    if (idx < HID * HID){
        float w = W2[idx];
        __nv_bfloat16 h = __float2bfloat16(w);
        g_W2h[idx] = h;
        g_W2l[idx] = __float2bfloat16(w - __bfloat162float(h));
        w = W3[idx];
        h = __float2bfloat16(w);
        g_W3h[idx] = h;
        g_W3l[idx] = __float2bfloat16(w - __bfloat162float(h));
    }
}

// ---------------------------------------------------------------------------
// Layer-1 recurrence: one thread per (n,i). Writes bf16 spikes + fr1.
// ---------------------------------------------------------------------------
__global__ void layer1_kernel(const float* __restrict__ x,
                              const float* __restrict__ W1,
                              const float* __restrict__ b1,
                              const float* __restrict__ mask1,
                              float* __restrict__ fr1)
{
    const int n = blockIdx.x;
    const int i = threadIdx.x;
    const float w = W1[i];
    const float b = b1[i];
    const float* __restrict__ xr = x + (size_t)n * T_STEPS;
    const float* __restrict__ mr = mask1 + (size_t)i * T_STEPS;

    float mem = 0.f, spike = 0.f, ss = 0.f;
    for (int t = 0; t < T_STEPS; ++t) {
        const float m_t = mr[t];
        const float new_mem = mem * DECAY * (1.f - spike) + xr[t] * w + b;
        if (m_t != 0.f) mem = new_mem;
        const float spk = (mem > THRESH) ? m_t : 0.f;
        g_S1b[((size_t)t * NBATCH + n) * HID + i] = __float2bfloat16(spk);
        ss += spk;
        spike = spk;
    }
    fr1[n * HID + i] = ss * (1.f / (float)T_STEPS);
}

// ---------------------------------------------------------------------------
// bf16 HMMA GEMM: C[m][j] = sum_k A[m][k]*(Wh[j][k]+Wl[j][k]), fp32 accum.
// A: [100352, 512] bf16; CTA tile 128x128, BK=64, 256 thr (8 warps, 64x32).
// Double-buffered cp.async; ldmatrix no-trans TN pattern; padded rows (144B).
// ---------------------------------------------------------------------------
__global__ void __launch_bounds__(256, 2)
gemm_bf16(int which)
{
    extern __shared__ char smem[];
    const __nv_bfloat16* __restrict__ A  = which ? g_S2b : g_S1b;
    const __nv_bfloat16* __restrict__ Bh = which ? g_W3h : g_W2h;
    const __nv_bfloat16* __restrict__ Bl = which ? g_W3l : g_W2l;

    const uint32_t sb = smem_u32(smem);
    const int tid  = threadIdx.x;
    const int lane = tid & 31;
    const int wrp  = tid >> 5;
    const int wm   = wrp & 1;          // 2 warp-rows of 64
    const int wn   = wrp >> 1;         // 4 warp-cols of 32
    const int n0 = blockIdx.x * BN;    // x = bn (4)  -> A reuse in L2
    const int m0 = blockIdx.y * BM;    // y = bm (784)

    // cp.async assignments: 4 chunks per tile per thread
    // chunk q = tid + 256*i : row = q>>3 (0..127), kc = q&7 (16B unit)
    auto load_stage = [&](int st, int c){
        const uint32_t base = sb + (uint32_t)st * STAGEB;
        #pragma unroll
        for (int i = 0; i < 4; ++i){
            const int q   = tid + 256 * i;
            const int row = q >> 3;
            const int kc  = q & 7;
            const uint32_t soff = (uint32_t)row * ROWB + (uint32_t)kc * 16u;
            const size_t gk = (size_t)c * BK + (size_t)kc * 8;
            cp16(base + soff,             A  + (size_t)(m0 + row) * KDIM + gk);
            cp16(base + TILEB + soff,     Bh + (size_t)(n0 + row) * KDIM + gk);
            cp16(base + 2u*TILEB + soff,  Bl + (size_t)(n0 + row) * KDIM + gk);
        }
        asm volatile("cp.async.commit_group;" ::: "memory");
    };

    float acc[4][4][4];
    #pragma unroll
    for (int mi = 0; mi < 4; ++mi)
        #pragma unroll
        for (int ni = 0; ni < 4; ++ni)
            #pragma unroll
            for (int q = 0; q < 4; ++q) acc[mi][ni][q] = 0.f;

    // ldmatrix per-thread base offsets (bytes)
    const uint32_t aOff = (uint32_t)(wm * 64 + (lane & 15)) * ROWB
                        + (uint32_t)((lane >> 4) << 3) * 2u;
    const uint32_t bOff = (uint32_t)(wn * 32 + (lane & 7)) * ROWB
                        + (uint32_t)(((lane >> 3) & 1) << 3) * 2u;

    load_stage(0, 0);

    const int NC = KDIM / BK;   // 8
    for (int c = 0; c < NC; ++c){
        if (c + 1 < NC){
            load_stage((c + 1) & 1, c + 1);
            asm volatile("cp.async.wait_group 1;" ::: "memory");
        } else {
            asm volatile("cp.async.wait_group 0;" ::: "memory");
        }
        __syncthreads();

        const uint32_t base = sb + (uint32_t)(c & 1) * STAGEB;
        const uint32_t aB = base + aOff;
        const uint32_t hB = base + TILEB + bOff;
        const uint32_t lB = base + 2u*TILEB + bOff;

        #pragma unroll
        for (int k16 = 0; k16 < 4; ++k16){
            uint32_t a[4][4], bh[4][2], bl[4][2];
            #pragma unroll
            for (int mi = 0; mi < 4; ++mi)
                ldsm4(a[mi], aB + (uint32_t)(mi * 16) * ROWB + (uint32_t)k16 * 32u);
            #pragma unroll
            for (int ni = 0; ni < 4; ++ni){
                ldsm2(bh[ni], hB + (uint32_t)(ni * 8) * ROWB + (uint32_t)k16 * 32u);
                ldsm2(bl[ni], lB + (uint32_t)(ni * 8) * ROWB + (uint32_t)k16 * 32u);
            }
            #pragma unroll
            for (int mi = 0; mi < 4; ++mi)
                #pragma unroll
                for (int ni = 0; ni < 4; ++ni){
                    mma_bf16(acc[mi][ni], a[mi], bh[ni]);
                    mma_bf16(acc[mi][ni], a[mi], bl[ni]);
                }
        }
        __syncthreads();
    }

    // Epilogue: fp32 stores to g_C (row stride 512)
    const int rbase = m0 + wm * 64 + (lane >> 2);
    const int cbase = n0 + wn * 32 + (lane & 3) * 2;
    #pragma unroll
    for (int mi = 0; mi < 4; ++mi){
        #pragma unroll
        for (int ni = 0; ni < 4; ++ni){
            float* p0 = g_C + (size_t)(rbase + mi * 16) * HID + cbase + ni * 8;
            float* p1 = p0 + 8 * HID;
            *(float2*)p0 = make_float2(acc[mi][ni][0], acc[mi][ni][1]);
            *(float2*)p1 = make_float2(acc[mi][ni][2], acc[mi][ni][3]);
        }
    }
}

// ---------------------------------------------------------------------------
// Layer-2/3 recurrence: reads g_C, writes bf16 spikes (layer 2) + fr.
// ---------------------------------------------------------------------------
__global__ void layerR_kernel(const float* __restrict__ bvec,
                              const float* __restrict__ mask,
                              float* __restrict__ fr,
                              int layer)
{
    const int n = blockIdx.x;
    const int j = threadIdx.x;
    const float bj = bvec[j];
    const float* __restrict__ mr = mask + (size_t)j * T_STEPS;

    float mem = 0.f, spike = 0.f, ss = 0.f;
    for (int t = 0; t < T_STEPS; ++t) {
        const float m_t = mr[t];
        const float c = g_C[((size_t)t * NBATCH + n) * HID + j];
        const float new_mem = mem * DECAY * (1.f - spike) + c + bj;
        if (m_t != 0.f) mem = new_mem;
        const float spk = (mem > THRESH) ? m_t : 0.f;
        if (layer == 2) g_S2b[((size_t)t * NBATCH + n) * HID + j] = __float2bfloat16(spk);
        ss += spk;
        spike = spk;
    }
    fr[n * HID + j] = ss * (1.f / (float)T_STEPS);
}

// ---------------------------------------------------------------------------
// Head: outputs[n][oc] = fr3[n] . W4[oc] + b4[oc]
// ---------------------------------------------------------------------------
__global__ void head_kernel(const float* __restrict__ fr3,
                            const float* __restrict__ W4,
                            const float* __restrict__ b4,
                            float* __restrict__ outputs)
{
    const int n = blockIdx.x;
    const int warp = threadIdx.x >> 5;
    const int lane = threadIdx.x & 31;
    const float* __restrict__ f = fr3 + (size_t)n * HID;
    const float* __restrict__ w = W4 + (size_t)warp * HID;
    float s = 0.f;
    for (int j = lane; j < HID; j += 32) s += f[j] * w[j];
#pragma unroll
    for (int o = 16; o > 0; o >>= 1) s += __shfl_xor_sync(0xffffffffu, s, o);
    if (lane == 0) outputs[n * OUTC + warp] = s + b4[warp];
}

// ---------------------------------------------------------------------------
// layer_fr[l] = mean(fr_l)
// ---------------------------------------------------------------------------
__global__ void lfr_kernel(const float* __restrict__ fr_all,
                           float* __restrict__ out3)
{
    const int l = blockIdx.x;
    const float* __restrict__ f = fr_all + (size_t)l * (NBATCH * HID);
    __shared__ float sh[256];
    float s = 0.f;
    for (int idx = threadIdx.x; idx < NBATCH * HID; idx += 256) s += f[idx];
    sh[threadIdx.x] = s;
    __syncthreads();
    for (int o = 128; o > 0; o >>= 1) {
        if (threadIdx.x < o) sh[threadIdx.x] += sh[threadIdx.x + o];
        __syncthreads();
    }
    if (threadIdx.x == 0) out3[l] = sh[0] * (1.f / (float)(NBATCH * HID));
}

// ---------------------------------------------------------------------------
// Launch. Inputs: 0:x 1:W1 2:b1 3:W2 4:b2 5:W3 6:b3 7:W4 8:b4 9..11:masks
// Output: outputs[1280], fr1[65536], fr2[65536], fr3[65536], layer_fr[3]
// ---------------------------------------------------------------------------
extern "C" void kernel_launch(void* const* d_in, const int* in_sizes, int n_in,
                              void* d_out, int out_size)
{
    const float* x     = (const float*)d_in[0];
    const float* W1    = (const float*)d_in[1];
    const float* b1    = (const float*)d_in[2];
    const float* W2    = (const float*)d_in[3];
    const float* b2    = (const float*)d_in[4];
    const float* W3    = (const float*)d_in[5];
    const float* b3    = (const float*)d_in[6];
    const float* W4    = (const float*)d_in[7];
    const float* b4    = (const float*)d_in[8];
    const float* mask1 = (const float*)d_in[9];
    const float* mask2 = (const float*)d_in[10];
    const float* mask3 = (const float*)d_in[11];

    float* out     = (float*)d_out;
    float* outputs = out;
    float* fr1     = out + NBATCH * OUTC;
    float* fr2     = fr1 + NBATCH * HID;
    float* fr3     = fr2 + NBATCH * HID;
    float* lfr     = fr3 + NBATCH * HID;

    cudaFuncSetAttribute(gemm_bf16, cudaFuncAttributeMaxDynamicSharedMemorySize, GEMM_SMEM);

    dim3 gemm_grid(4, T_STEPS);   // x = bn, y = bm (A tiles reused across x in L2)

    split_kernel<<<(HID*HID + 255)/256, 256>>>(W2, W3);
    layer1_kernel<<<NBATCH, HID>>>(x, W1, b1, mask1, fr1);
    gemm_bf16<<<gemm_grid, 256, GEMM_SMEM>>>(0);
    layerR_kernel<<<NBATCH, HID>>>(b2, mask2, fr2, 2);
    gemm_bf16<<<gemm_grid, 256, GEMM_SMEM>>>(1);
    layerR_kernel<<<NBATCH, HID>>>(b3, mask3, fr3, 3);
    head_kernel<<<NBATCH, 320>>>(fr3, W4, b4, outputs);
    lfr_kernel<<<3, 256>>>(fr1, lfr);
}

// round 4
// speedup vs baseline: 3.4566x; 1.3290x over previous
#include <cuda_runtime.h>
#include <cuda_bf16.h>
#include <cstdint>
#include <cstddef>

// Problem constants
#define T_STEPS 784
#define NBATCH  128
#define HID     512
#define OUTC    10
#define DECAY   0.2f
#define THRESH  0.5f
#define KDIM    512

// GEMM tiling
#define BM 128
#define BN 128
#define BK 64
#define ROWB 144u              // smem bytes per row: 64 bf16 (128B) + 16B pad
#define TILEB (128u * ROWB)    // 18432 B
#define STAGEB (3u * TILEB)    // A + Wh + Wl per stage
#define GEMM_SMEM (2u * STAGEB)  // 110592 B double-buffered

#define SEQ_ELEMS ((size_t)T_STEPS * NBATCH * HID)
__device__ __nv_bfloat16 g_S1b[SEQ_ELEMS];   // layer-1 spikes [t][n][i] (exact 0/1)
__device__ __nv_bfloat16 g_S2b[SEQ_ELEMS];   // layer-2 spikes
__device__ float         g_C  [SEQ_ELEMS];   // GEMM output [t][n][j] fp32
__device__ __nv_bfloat16 g_W2h[HID*HID], g_W2l[HID*HID];
__device__ __nv_bfloat16 g_W3h[HID*HID], g_W3l[HID*HID];
__device__ float         g_maskT[3][T_STEPS * HID];   // transposed masks [T][H]

// ---------------------------------------------------------------------------
// PTX helpers (sm_80-era: ldmatrix / mma.sync / cp.async — safe for sm_103)
// ---------------------------------------------------------------------------
__device__ __forceinline__ uint32_t smem_u32(const void* p){
    uint32_t a;
    asm("{ .reg .u64 t; cvta.to.shared.u64 t, %1; cvt.u32.u64 %0, t; }" : "=r"(a) : "l"(p));
    return a;
}
__device__ __forceinline__ void cp16(uint32_t saddr, const void* gaddr){
    asm volatile("cp.async.cg.shared.global [%0], [%1], 16;" :: "r"(saddr), "l"(gaddr));
}
__device__ __forceinline__ void ldsm4(uint32_t* r, uint32_t addr){
    asm volatile("ldmatrix.sync.aligned.m8n8.x4.shared.b16 {%0,%1,%2,%3}, [%4];"
        : "=r"(r[0]), "=r"(r[1]), "=r"(r[2]), "=r"(r[3]) : "r"(addr));
}
__device__ __forceinline__ void ldsm2(uint32_t* r, uint32_t addr){
    asm volatile("ldmatrix.sync.aligned.m8n8.x2.shared.b16 {%0,%1}, [%2];"
        : "=r"(r[0]), "=r"(r[1]) : "r"(addr));
}
__device__ __forceinline__ void mma_bf16(float* c, const uint32_t* a, const uint32_t* b){
    asm volatile(
        "mma.sync.aligned.m16n8k16.row.col.f32.bf16.bf16.f32 "
        "{%0,%1,%2,%3}, {%4,%5,%6,%7}, {%8,%9}, {%0,%1,%2,%3};"
        : "+f"(c[0]), "+f"(c[1]), "+f"(c[2]), "+f"(c[3])
        : "r"(a[0]), "r"(a[1]), "r"(a[2]), "r"(a[3]), "r"(b[0]), "r"(b[1]));
}

// ---------------------------------------------------------------------------
// Weight split: W -> hi(bf16) + lo(bf16); residual ~2^-16 |w|
// ---------------------------------------------------------------------------
__global__ void split_kernel(const float* __restrict__ W2, const float* __restrict__ W3){
    int idx = blockIdx.x * blockDim.x + threadIdx.x;
    if (idx < HID * HID){
        float w = W2[idx];
        __nv_bfloat16 h = __float2bfloat16(w);
        g_W2h[idx] = h;
        g_W2l[idx] = __float2bfloat16(w - __bfloat162float(h));
        w = W3[idx];
        h = __float2bfloat16(w);
        g_W3h[idx] = h;
        g_W3l[idx] = __float2bfloat16(w - __bfloat162float(h));
    }
}

// ---------------------------------------------------------------------------
// Mask transpose: [H][T] -> [T][H] (coalesced recurrence-side reads).
// grid (H/32, ceil(T/32), 3), block (32, 32)
// ---------------------------------------------------------------------------
__global__ void maskT_kernel(const float* __restrict__ m1,
                             const float* __restrict__ m2,
                             const float* __restrict__ m3)
{
    __shared__ float tile[32][33];
    const float* src = (blockIdx.z == 0) ? m1 : (blockIdx.z == 1) ? m2 : m3;
    const int jb = blockIdx.x * 32;
    const int tb = blockIdx.y * 32;
    const int tx = threadIdx.x, ty = threadIdx.y;

    if (tb + tx < T_STEPS)
        tile[ty][tx] = src[(size_t)(jb + ty) * T_STEPS + tb + tx];
    __syncthreads();
    if (tb + ty < T_STEPS)
        g_maskT[blockIdx.z][(size_t)(tb + ty) * HID + jb + tx] = tile[tx][ty];
}

// ---------------------------------------------------------------------------
// Layer-1 recurrence, pipelined: grid (NBATCH, HID/128), block 128.
// 8-step register double-buffer; mask reads via g_maskT (coalesced).
// ---------------------------------------------------------------------------
__global__ void layer1_kernel(const float* __restrict__ x,
                              const float* __restrict__ W1,
                              const float* __restrict__ b1,
                              float* __restrict__ fr1)
{
    const int n = blockIdx.x;
    const int i = blockIdx.y * 128 + threadIdx.x;
    const float w = W1[i];
    const float b = b1[i];
    const float* __restrict__ xr = x + (size_t)n * T_STEPS;
    const float* __restrict__ mk = g_maskT[0];
    __nv_bfloat16* __restrict__ sOut = g_S1b + (size_t)n * HID + i;
    const size_t cstr = (size_t)NBATCH * HID;

    float xb[2][8], mb[2][8];
    #pragma unroll
    for (int u = 0; u < 8; ++u){
        xb[0][u] = xr[u];
        mb[0][u] = mk[(size_t)u * HID + i];
    }

    float mem = 0.f, spike = 0.f, ss = 0.f;
    for (int tc = 0; tc < T_STEPS / 8; ++tc){
        const int cur = tc & 1, nxt = cur ^ 1;
        const int tb = tc * 8;
        if (tc + 1 < T_STEPS / 8){
            #pragma unroll
            for (int u = 0; u < 8; ++u){
                xb[nxt][u] = xr[tb + 8 + u];
                mb[nxt][u] = mk[(size_t)(tb + 8 + u) * HID + i];
            }
        }
        #pragma unroll
        for (int u = 0; u < 8; ++u){
            const float m_t = mb[cur][u];
            const float new_mem = mem * DECAY * (1.f - spike) + xb[cur][u] * w + b;
            if (m_t != 0.f) mem = new_mem;
            const float spk = (mem > THRESH) ? m_t : 0.f;
            sOut[(size_t)(tb + u) * cstr] = __float2bfloat16(spk);
            ss += spk;
            spike = spk;
        }
    }
    fr1[n * HID + i] = ss * (1.f / (float)T_STEPS);
}

// ---------------------------------------------------------------------------
// bf16 HMMA GEMM: C[m][j] = sum_k A[m][k]*(Wh[j][k]+Wl[j][k]), fp32 accum.
// ---------------------------------------------------------------------------
__global__ void __launch_bounds__(256, 2)
gemm_bf16(int which)
{
    extern __shared__ char smem[];
    const __nv_bfloat16* __restrict__ A  = which ? g_S2b : g_S1b;
    const __nv_bfloat16* __restrict__ Bh = which ? g_W3h : g_W2h;
    const __nv_bfloat16* __restrict__ Bl = which ? g_W3l : g_W2l;

    const uint32_t sb = smem_u32(smem);
    const int tid  = threadIdx.x;
    const int lane = tid & 31;
    const int wrp  = tid >> 5;
    const int wm   = wrp & 1;          // 2 warp-rows of 64
    const int wn   = wrp >> 1;         // 4 warp-cols of 32
    const int n0 = blockIdx.x * BN;    // x = bn (4)  -> A reuse in L2
    const int m0 = blockIdx.y * BM;    // y = bm (784)

    auto load_stage = [&](int st, int c){
        const uint32_t base = sb + (uint32_t)st * STAGEB;
        #pragma unroll
        for (int i = 0; i < 4; ++i){
            const int q   = tid + 256 * i;
            const int row = q >> 3;
            const int kc  = q & 7;
            const uint32_t soff = (uint32_t)row * ROWB + (uint32_t)kc * 16u;
            const size_t gk = (size_t)c * BK + (size_t)kc * 8;
            cp16(base + soff,             A  + (size_t)(m0 + row) * KDIM + gk);
            cp16(base + TILEB + soff,     Bh + (size_t)(n0 + row) * KDIM + gk);
            cp16(base + 2u*TILEB + soff,  Bl + (size_t)(n0 + row) * KDIM + gk);
        }
        asm volatile("cp.async.commit_group;" ::: "memory");
    };

    float acc[4][4][4];
    #pragma unroll
    for (int mi = 0; mi < 4; ++mi)
        #pragma unroll
        for (int ni = 0; ni < 4; ++ni)
            #pragma unroll
            for (int q = 0; q < 4; ++q) acc[mi][ni][q] = 0.f;

    const uint32_t aOff = (uint32_t)(wm * 64 + (lane & 15)) * ROWB
                        + (uint32_t)((lane >> 4) << 3) * 2u;
    const uint32_t bOff = (uint32_t)(wn * 32 + (lane & 7)) * ROWB
                        + (uint32_t)(((lane >> 3) & 1) << 3) * 2u;

    load_stage(0, 0);

    const int NC = KDIM / BK;   // 8
    for (int c = 0; c < NC; ++c){
        if (c + 1 < NC){
            load_stage((c + 1) & 1, c + 1);
            asm volatile("cp.async.wait_group 1;" ::: "memory");
        } else {
            asm volatile("cp.async.wait_group 0;" ::: "memory");
        }
        __syncthreads();

        const uint32_t base = sb + (uint32_t)(c & 1) * STAGEB;
        const uint32_t aB = base + aOff;
        const uint32_t hB = base + TILEB + bOff;
        const uint32_t lB = base + 2u*TILEB + bOff;

        #pragma unroll
        for (int k16 = 0; k16 < 4; ++k16){
            uint32_t a[4][4], bh[4][2], bl[4][2];
            #pragma unroll
            for (int mi = 0; mi < 4; ++mi)
                ldsm4(a[mi], aB + (uint32_t)(mi * 16) * ROWB + (uint32_t)k16 * 32u);
            #pragma unroll
            for (int ni = 0; ni < 4; ++ni){
                ldsm2(bh[ni], hB + (uint32_t)(ni * 8) * ROWB + (uint32_t)k16 * 32u);
                ldsm2(bl[ni], lB + (uint32_t)(ni * 8) * ROWB + (uint32_t)k16 * 32u);
            }
            #pragma unroll
            for (int mi = 0; mi < 4; ++mi)
                #pragma unroll
                for (int ni = 0; ni < 4; ++ni){
                    mma_bf16(acc[mi][ni], a[mi], bh[ni]);
                    mma_bf16(acc[mi][ni], a[mi], bl[ni]);
                }
        }
        __syncthreads();
    }

    const int rbase = m0 + wm * 64 + (lane >> 2);
    const int cbase = n0 + wn * 32 + (lane & 3) * 2;
    #pragma unroll
    for (int mi = 0; mi < 4; ++mi){
        #pragma unroll
        for (int ni = 0; ni < 4; ++ni){
            float* p0 = g_C + (size_t)(rbase + mi * 16) * HID + cbase + ni * 8;
            float* p1 = p0 + 8 * HID;
            *(float2*)p0 = make_float2(acc[mi][ni][0], acc[mi][ni][1]);
            *(float2*)p1 = make_float2(acc[mi][ni][2], acc[mi][ni][3]);
        }
    }
}

// ---------------------------------------------------------------------------
// Layer-2/3 recurrence, pipelined: grid (NBATCH, HID/128), block 128.
// maskSel: 1 or 2 (index into g_maskT). layer==2 stores bf16 spikes.
// ---------------------------------------------------------------------------
__global__ void layerR_kernel(const float* __restrict__ bvec,
                              float* __restrict__ fr,
                              int maskSel, int layer)
{
    const int n = blockIdx.x;
    const int j = blockIdx.y * 128 + threadIdx.x;
    const float bj = bvec[j];
    const float* __restrict__ mk = g_maskT[maskSel];
    const size_t cstr = (size_t)NBATCH * HID;
    const float* __restrict__ cPtr = g_C + (size_t)n * HID + j;
    __nv_bfloat16* __restrict__ sOut = g_S2b + (size_t)n * HID + j;

    float cb[2][8], mb[2][8];
    #pragma unroll
    for (int u = 0; u < 8; ++u){
        cb[0][u] = cPtr[(size_t)u * cstr];
        mb[0][u] = mk[(size_t)u * HID + j];
    }

    float mem = 0.f, spike = 0.f, ss = 0.f;
    for (int tc = 0; tc < T_STEPS / 8; ++tc){
        const int cur = tc & 1, nxt = cur ^ 1;
        const int tb = tc * 8;
        if (tc + 1 < T_STEPS / 8){
            #pragma unroll
            for (int u = 0; u < 8; ++u){
                cb[nxt][u] = cPtr[(size_t)(tb + 8 + u) * cstr];
                mb[nxt][u] = mk[(size_t)(tb + 8 + u) * HID + j];
            }
        }
        #pragma unroll
        for (int u = 0; u < 8; ++u){
            const float m_t = mb[cur][u];
            const float new_mem = mem * DECAY * (1.f - spike) + cb[cur][u] + bj;
            if (m_t != 0.f) mem = new_mem;
            const float spk = (mem > THRESH) ? m_t : 0.f;
            if (layer == 2) sOut[(size_t)(tb + u) * cstr] = __float2bfloat16(spk);
            ss += spk;
            spike = spk;
        }
    }
    fr[n * HID + j] = ss * (1.f / (float)T_STEPS);
}

// ---------------------------------------------------------------------------
// Head: outputs[n][oc] = fr3[n] . W4[oc] + b4[oc]
// ---------------------------------------------------------------------------
__global__ void head_kernel(const float* __restrict__ fr3,
                            const float* __restrict__ W4,
                            const float* __restrict__ b4,
                            float* __restrict__ outputs)
{
    const int n = blockIdx.x;
    const int warp = threadIdx.x >> 5;
    const int lane = threadIdx.x & 31;
    const float* __restrict__ f = fr3 + (size_t)n * HID;
    const float* __restrict__ w = W4 + (size_t)warp * HID;
    float s = 0.f;
    for (int j = lane; j < HID; j += 32) s += f[j] * w[j];
#pragma unroll
    for (int o = 16; o > 0; o >>= 1) s += __shfl_xor_sync(0xffffffffu, s, o);
    if (lane == 0) outputs[n * OUTC + warp] = s + b4[warp];
}

// ---------------------------------------------------------------------------
// layer_fr[l] = mean(fr_l)
// ---------------------------------------------------------------------------
__global__ void lfr_kernel(const float* __restrict__ fr_all,
                           float* __restrict__ out3)
{
    const int l = blockIdx.x;
    const float* __restrict__ f = fr_all + (size_t)l * (NBATCH * HID);
    __shared__ float sh[256];
    float s = 0.f;
    for (int idx = threadIdx.x; idx < NBATCH * HID; idx += 256) s += f[idx];
    sh[threadIdx.x] = s;
    __syncthreads();
    for (int o = 128; o > 0; o >>= 1) {
        if (threadIdx.x < o) sh[threadIdx.x] += sh[threadIdx.x + o];
        __syncthreads();
    }
    if (threadIdx.x == 0) out3[l] = sh[0] * (1.f / (float)(NBATCH * HID));
}

// ---------------------------------------------------------------------------
// Launch. Inputs: 0:x 1:W1 2:b1 3:W2 4:b2 5:W3 6:b3 7:W4 8:b4 9..11:masks
// Output: outputs[1280], fr1[65536], fr2[65536], fr3[65536], layer_fr[3]
// ---------------------------------------------------------------------------
extern "C" void kernel_launch(void* const* d_in, const int* in_sizes, int n_in,
                              void* d_out, int out_size)
{
    const float* x     = (const float*)d_in[0];
    const float* W1    = (const float*)d_in[1];
    const float* b1    = (const float*)d_in[2];
    const float* W2    = (const float*)d_in[3];
    const float* b2    = (const float*)d_in[4];
    const float* W3    = (const float*)d_in[5];
    const float* b3    = (const float*)d_in[6];
    const float* W4    = (const float*)d_in[7];
    const float* b4    = (const float*)d_in[8];
    const float* mask1 = (const float*)d_in[9];
    const float* mask2 = (const float*)d_in[10];
    const float* mask3 = (const float*)d_in[11];

    float* out     = (float*)d_out;
    float* outputs = out;
    float* fr1     = out + NBATCH * OUTC;
    float* fr2     = fr1 + NBATCH * HID;
    float* fr3     = fr2 + NBATCH * HID;
    float* lfr     = fr3 + NBATCH * HID;

    cudaFuncSetAttribute(gemm_bf16, cudaFuncAttributeMaxDynamicSharedMemorySize, GEMM_SMEM);

    dim3 gemm_grid(4, T_STEPS);       // x = bn, y = bm (A tiles reused across x in L2)
    dim3 rec_grid(NBATCH, HID / 128); // 512 CTAs, 128 threads
    dim3 mt_grid(HID / 32, (T_STEPS + 31) / 32, 3);

    maskT_kernel<<<mt_grid, dim3(32, 32)>>>(mask1, mask2, mask3);
    split_kernel<<<(HID*HID + 255)/256, 256>>>(W2, W3);
    layer1_kernel<<<rec_grid, 128>>>(x, W1, b1, fr1);
    gemm_bf16<<<gemm_grid, 256, GEMM_SMEM>>>(0);
    layerR_kernel<<<rec_grid, 128>>>(b2, fr2, 1, 2);
    gemm_bf16<<<gemm_grid, 256, GEMM_SMEM>>>(1);
    layerR_kernel<<<rec_grid, 128>>>(b3, fr3, 2, 3);
    head_kernel<<<NBATCH, 320>>>(fr3, W4, b4, outputs);
    lfr_kernel<<<3, 256>>>(fr1, lfr);
}

// round 5
// speedup vs baseline: 3.5179x; 1.0177x over previous
#include <cuda_runtime.h>
#include <cuda_bf16.h>
#include <cstdint>
#include <cstddef>

// Problem constants
#define T_STEPS 784
#define NBATCH  128
#define HID     512
#define OUTC    10
#define DECAY   0.2f
#define THRESH  0.5f
#define KDIM    512

// GEMM tiling
#define BM 128
#define BN 128
#define BK 64
#define ROWB 144u              // smem bytes per row: 64 bf16 (128B) + 16B pad
#define TILEB (128u * ROWB)    // 18432 B
#define STAGEB (3u * TILEB)    // A + Wh + Wl per stage
#define GEMM_SMEM (2u * STAGEB)  // 110592 B double-buffered

// Recurrence pipelining
#define UNR 16                 // 784 = 49 * 16

#define SEQ_ELEMS ((size_t)T_STEPS * NBATCH * HID)
__device__ __nv_bfloat16 g_S1b[SEQ_ELEMS];   // layer-1 spikes [t][n][i] (exact 0/1)
__device__ __nv_bfloat16 g_S2b[SEQ_ELEMS];   // layer-2 spikes
__device__ float         g_C  [SEQ_ELEMS];   // GEMM output [t][n][j] fp32
__device__ __nv_bfloat16 g_W2h[HID*HID], g_W2l[HID*HID];
__device__ __nv_bfloat16 g_W3h[HID*HID], g_W3l[HID*HID];
__device__ float         g_maskT[3][T_STEPS * HID];   // transposed masks [T][H]

// ---------------------------------------------------------------------------
// PTX helpers (sm_80-era: ldmatrix / mma.sync / cp.async — safe for sm_103)
// ---------------------------------------------------------------------------
__device__ __forceinline__ uint32_t smem_u32(const void* p){
    uint32_t a;
    asm("{ .reg .u64 t; cvta.to.shared.u64 t, %1; cvt.u32.u64 %0, t; }" : "=r"(a) : "l"(p));
    return a;
}
__device__ __forceinline__ void cp16(uint32_t saddr, const void* gaddr){
    asm volatile("cp.async.cg.shared.global [%0], [%1], 16;" :: "r"(saddr), "l"(gaddr));
}
__device__ __forceinline__ void ldsm4(uint32_t* r, uint32_t addr){
    asm volatile("ldmatrix.sync.aligned.m8n8.x4.shared.b16 {%0,%1,%2,%3}, [%4];"
        : "=r"(r[0]), "=r"(r[1]), "=r"(r[2]), "=r"(r[3]) : "r"(addr));
}
__device__ __forceinline__ void mma_bf16(float* c, const uint32_t* a, const uint32_t* b){
    asm volatile(
        "mma.sync.aligned.m16n8k16.row.col.f32.bf16.bf16.f32 "
        "{%0,%1,%2,%3}, {%4,%5,%6,%7}, {%8,%9}, {%0,%1,%2,%3};"
        : "+f"(c[0]), "+f"(c[1]), "+f"(c[2]), "+f"(c[3])
        : "r"(a[0]), "r"(a[1]), "r"(a[2]), "r"(a[3]), "r"(b[0]), "r"(b[1]));
}

// ---------------------------------------------------------------------------
// Weight split: W -> hi(bf16) + lo(bf16); residual ~2^-16 |w|
// ---------------------------------------------------------------------------
__global__ void split_kernel(const float* __restrict__ W2, const float* __restrict__ W3){
    int idx = blockIdx.x * blockDim.x + threadIdx.x;
    if (idx < HID * HID){
        float w = W2[idx];
        __nv_bfloat16 h = __float2bfloat16(w);
        g_W2h[idx] = h;
        g_W2l[idx] = __float2bfloat16(w - __bfloat162float(h));
        w = W3[idx];
        h = __float2bfloat16(w);
        g_W3h[idx] = h;
        g_W3l[idx] = __float2bfloat16(w - __bfloat162float(h));
    }
}

// ---------------------------------------------------------------------------
// Mask transpose: [H][T] -> [T][H]
// ---------------------------------------------------------------------------
__global__ void maskT_kernel(const float* __restrict__ m1,
                             const float* __restrict__ m2,
                             const float* __restrict__ m3)
{
    __shared__ float tile[32][33];
    const float* src = (blockIdx.z == 0) ? m1 : (blockIdx.z == 1) ? m2 : m3;
    const int jb = blockIdx.x * 32;
    const int tb = blockIdx.y * 32;
    const int tx = threadIdx.x, ty = threadIdx.y;

    if (tb + tx < T_STEPS)
        tile[ty][tx] = src[(size_t)(jb + ty) * T_STEPS + tb + tx];
    __syncthreads();
    if (tb + ty < T_STEPS)
        g_maskT[blockIdx.z][(size_t)(tb + ty) * HID + jb + tx] = tile[tx][ty];
}

// ---------------------------------------------------------------------------
// Layer-1 recurrence, 16-step register double-buffer.
// grid (NBATCH, HID/128), block 128.
// ---------------------------------------------------------------------------
__global__ void layer1_kernel(const float* __restrict__ x,
                              const float* __restrict__ W1,
                              const float* __restrict__ b1,
                              float* __restrict__ fr1)
{
    const int n = blockIdx.x;
    const int i = blockIdx.y * 128 + threadIdx.x;
    const float w = W1[i];
    const float b = b1[i];
    const float* __restrict__ xr = x + (size_t)n * T_STEPS;
    const float* __restrict__ mk = g_maskT[0];
    __nv_bfloat16* __restrict__ sOut = g_S1b + (size_t)n * HID + i;
    const size_t cstr = (size_t)NBATCH * HID;

    float xb[2][UNR], mb[2][UNR];
    #pragma unroll
    for (int u = 0; u < UNR; ++u){
        xb[0][u] = xr[u];
        mb[0][u] = mk[(size_t)u * HID + i];
    }

    float mem = 0.f, spike = 0.f, ss = 0.f;
    for (int tc = 0; tc < T_STEPS / UNR; ++tc){
        const int cur = tc & 1, nxt = cur ^ 1;
        const int tb = tc * UNR;
        if (tc + 1 < T_STEPS / UNR){
            #pragma unroll
            for (int u = 0; u < UNR; ++u){
                xb[nxt][u] = xr[tb + UNR + u];
                mb[nxt][u] = mk[(size_t)(tb + UNR + u) * HID + i];
            }
        }
        #pragma unroll
        for (int u = 0; u < UNR; ++u){
            const float m_t = mb[cur][u];
            const float new_mem = mem * DECAY * (1.f - spike) + xb[cur][u] * w + b;
            if (m_t != 0.f) mem = new_mem;
            const float spk = (mem > THRESH) ? m_t : 0.f;
            sOut[(size_t)(tb + u) * cstr] = __float2bfloat16(spk);
            ss += spk;
            spike = spk;
        }
    }
    fr1[n * HID + i] = ss * (1.f / (float)T_STEPS);
}

// ---------------------------------------------------------------------------
// bf16 HMMA GEMM: C[m][j] = sum_k A[m][k]*(Wh[j][k]+Wl[j][k]), fp32 accum.
// B fragments via ldmatrix.x4 (n16 x k16 per instruction).
// ---------------------------------------------------------------------------
__global__ void __launch_bounds__(256, 2)
gemm_bf16(int which)
{
    extern __shared__ char smem[];
    const __nv_bfloat16* __restrict__ A  = which ? g_S2b : g_S1b;
    const __nv_bfloat16* __restrict__ Bh = which ? g_W3h : g_W2h;
    const __nv_bfloat16* __restrict__ Bl = which ? g_W3l : g_W2l;

    const uint32_t sb = smem_u32(smem);
    const int tid  = threadIdx.x;
    const int lane = tid & 31;
    const int wrp  = tid >> 5;
    const int wm   = wrp & 1;          // 2 warp-rows of 64
    const int wn   = wrp >> 1;         // 4 warp-cols of 32
    const int n0 = blockIdx.x * BN;    // x = bn (4)  -> A reuse in L2
    const int m0 = blockIdx.y * BM;    // y = bm (784)

    auto load_stage = [&](int st, int c){
        const uint32_t base = sb + (uint32_t)st * STAGEB;
        #pragma unroll
        for (int i = 0; i < 4; ++i){
            const int q   = tid + 256 * i;
            const int row = q >> 3;
            const int kc  = q & 7;
            const uint32_t soff = (uint32_t)row * ROWB + (uint32_t)kc * 16u;
            const size_t gk = (size_t)c * BK + (size_t)kc * 8;
            cp16(base + soff,             A  + (size_t)(m0 + row) * KDIM + gk);
            cp16(base + TILEB + soff,     Bh + (size_t)(n0 + row) * KDIM + gk);
            cp16(base + 2u*TILEB + soff,  Bl + (size_t)(n0 + row) * KDIM + gk);
        }
        asm volatile("cp.async.commit_group;" ::: "memory");
    };

    float acc[4][4][4];
    #pragma unroll
    for (int mi = 0; mi < 4; ++mi)
        #pragma unroll
        for (int ni = 0; ni < 4; ++ni)
            #pragma unroll
            for (int q = 0; q < 4; ++q) acc[mi][ni][q] = 0.f;

    // A ldsm4: rows (lane&15), k-halves by lane>>4
    const uint32_t aOff = (uint32_t)(wm * 64 + (lane & 15)) * ROWB
                        + (uint32_t)((lane >> 4) << 3) * 2u;
    // B ldsm4: matrices [n8(p*16+0..7) klo, same khi, n8(p*16+8..15) klo, khi]
    //   lanes 0-7: n-row, kbase | 8-15: n-row, k+8 | 16-23: n-row+8, kbase | 24-31: n-row+8, k+8
    const uint32_t bOff = (uint32_t)(wn * 32 + ((lane >> 4) << 3) + (lane & 7)) * ROWB
                        + (uint32_t)(((lane >> 3) & 1) << 4);

    load_stage(0, 0);

    const int NC = KDIM / BK;   // 8
    for (int c = 0; c < NC; ++c){
        if (c + 1 < NC){
            load_stage((c + 1) & 1, c + 1);
            asm volatile("cp.async.wait_group 1;" ::: "memory");
        } else {
            asm volatile("cp.async.wait_group 0;" ::: "memory");
        }
        __syncthreads();

        const uint32_t base = sb + (uint32_t)(c & 1) * STAGEB;
        const uint32_t aB = base + aOff;
        const uint32_t hB = base + TILEB + bOff;
        const uint32_t lB = base + 2u*TILEB + bOff;

        #pragma unroll
        for (int k16 = 0; k16 < 4; ++k16){
            uint32_t a[4][4], bh[2][4], bl[2][4];
            #pragma unroll
            for (int mi = 0; mi < 4; ++mi)
                ldsm4(a[mi], aB + (uint32_t)(mi * 16) * ROWB + (uint32_t)k16 * 32u);
            #pragma unroll
            for (int p = 0; p < 2; ++p){
                ldsm4(bh[p], hB + (uint32_t)(p * 16) * ROWB + (uint32_t)k16 * 32u);
                ldsm4(bl[p], lB + (uint32_t)(p * 16) * ROWB + (uint32_t)k16 * 32u);
            }
            #pragma unroll
            for (int mi = 0; mi < 4; ++mi)
                #pragma unroll
                for (int ni = 0; ni < 4; ++ni){
                    mma_bf16(acc[mi][ni], a[mi], &bh[ni >> 1][(ni & 1) * 2]);
                    mma_bf16(acc[mi][ni], a[mi], &bl[ni >> 1][(ni & 1) * 2]);
                }
        }
        __syncthreads();
    }

    const int rbase = m0 + wm * 64 + (lane >> 2);
    const int cbase = n0 + wn * 32 + (lane & 3) * 2;
    #pragma unroll
    for (int mi = 0; mi < 4; ++mi){
        #pragma unroll
        for (int ni = 0; ni < 4; ++ni){
            float* p0 = g_C + (size_t)(rbase + mi * 16) * HID + cbase + ni * 8;
            float* p1 = p0 + 8 * HID;
            *(float2*)p0 = make_float2(acc[mi][ni][0], acc[mi][ni][1]);
            *(float2*)p1 = make_float2(acc[mi][ni][2], acc[mi][ni][3]);
        }
    }
}

// ---------------------------------------------------------------------------
// Layer-2/3 recurrence, 16-step register double-buffer.
// grid (NBATCH, HID/128), block 128. layer==2 stores bf16 spikes.
// ---------------------------------------------------------------------------
__global__ void layerR_kernel(const float* __restrict__ bvec,
                              float* __restrict__ fr,
                              int maskSel, int layer)
{
    const int n = blockIdx.x;
    const int j = blockIdx.y * 128 + threadIdx.x;
    const float bj = bvec[j];
    const float* __restrict__ mk = g_maskT[maskSel];
    const size_t cstr = (size_t)NBATCH * HID;
    const float* __restrict__ cPtr = g_C + (size_t)n * HID + j;
    __nv_bfloat16* __restrict__ sOut = g_S2b + (size_t)n * HID + j;

    float cb[2][UNR], mb[2][UNR];
    #pragma unroll
    for (int u = 0; u < UNR; ++u){
        cb[0][u] = cPtr[(size_t)u * cstr];
        mb[0][u] = mk[(size_t)u * HID + j];
    }

    float mem = 0.f, spike = 0.f, ss = 0.f;
    for (int tc = 0; tc < T_STEPS / UNR; ++tc){
        const int cur = tc & 1, nxt = cur ^ 1;
        const int tb = tc * UNR;
        if (tc + 1 < T_STEPS / UNR){
            #pragma unroll
            for (int u = 0; u < UNR; ++u){
                cb[nxt][u] = cPtr[(size_t)(tb + UNR + u) * cstr];
                mb[nxt][u] = mk[(size_t)(tb + UNR + u) * HID + j];
            }
        }
        #pragma unroll
        for (int u = 0; u < UNR; ++u){
            const float m_t = mb[cur][u];
            const float new_mem = mem * DECAY * (1.f - spike) + cb[cur][u] + bj;
            if (m_t != 0.f) mem = new_mem;
            const float spk = (mem > THRESH) ? m_t : 0.f;
            if (layer == 2) sOut[(size_t)(tb + u) * cstr] = __float2bfloat16(spk);
            ss += spk;
            spike = spk;
        }
    }
    fr[n * HID + j] = ss * (1.f / (float)T_STEPS);
}

// ---------------------------------------------------------------------------
// Head: outputs[n][oc] = fr3[n] . W4[oc] + b4[oc]
// ---------------------------------------------------------------------------
__global__ void head_kernel(const float* __restrict__ fr3,
                            const float* __restrict__ W4,
                            const float* __restrict__ b4,
                            float* __restrict__ outputs)
{
    const int n = blockIdx.x;
    const int warp = threadIdx.x >> 5;
    const int lane = threadIdx.x & 31;
    const float* __restrict__ f = fr3 + (size_t)n * HID;
    const float* __restrict__ w = W4 + (size_t)warp * HID;
    float s = 0.f;
    for (int j = lane; j < HID; j += 32) s += f[j] * w[j];
#pragma unroll
    for (int o = 16; o > 0; o >>= 1) s += __shfl_xor_sync(0xffffffffu, s, o);
    if (lane == 0) outputs[n * OUTC + warp] = s + b4[warp];
}

// ---------------------------------------------------------------------------
// layer_fr[l] = mean(fr_l)
// ---------------------------------------------------------------------------
__global__ void lfr_kernel(const float* __restrict__ fr_all,
                           float* __restrict__ out3)
{
    const int l = blockIdx.x;
    const float* __restrict__ f = fr_all + (size_t)l * (NBATCH * HID);
    __shared__ float sh[256];
    float s = 0.f;
    for (int idx = threadIdx.x; idx < NBATCH * HID; idx += 256) s += f[idx];
    sh[threadIdx.x] = s;
    __syncthreads();
    for (int o = 128; o > 0; o >>= 1) {
        if (threadIdx.x < o) sh[threadIdx.x] += sh[threadIdx.x + o];
        __syncthreads();
    }
    if (threadIdx.x == 0) out3[l] = sh[0] * (1.f / (float)(NBATCH * HID));
}

// ---------------------------------------------------------------------------
// Launch. Inputs: 0:x 1:W1 2:b1 3:W2 4:b2 5:W3 6:b3 7:W4 8:b4 9..11:masks
// Output: outputs[1280], fr1[65536], fr2[65536], fr3[65536], layer_fr[3]
// ---------------------------------------------------------------------------
extern "C" void kernel_launch(void* const* d_in, const int* in_sizes, int n_in,
                              void* d_out, int out_size)
{
    const float* x     = (const float*)d_in[0];
    const float* W1    = (const float*)d_in[1];
    const float* b1    = (const float*)d_in[2];
    const float* W2    = (const float*)d_in[3];
    const float* b2    = (const float*)d_in[4];
    const float* W3    = (const float*)d_in[5];
    const float* b3    = (const float*)d_in[6];
    const float* W4    = (const float*)d_in[7];
    const float* b4    = (const float*)d_in[8];
    const float* mask1 = (const float*)d_in[9];
    const float* mask2 = (const float*)d_in[10];
    const float* mask3 = (const float*)d_in[11];

    float* out     = (float*)d_out;
    float* outputs = out;
    float* fr1     = out + NBATCH * OUTC;
    float* fr2     = fr1 + NBATCH * HID;
    float* fr3     = fr2 + NBATCH * HID;
    float* lfr     = fr3 + NBATCH * HID;

    cudaFuncSetAttribute(gemm_bf16, cudaFuncAttributeMaxDynamicSharedMemorySize, GEMM_SMEM);

    dim3 gemm_grid(4, T_STEPS);       // x = bn, y = bm (A tiles reused across x in L2)
    dim3 rec_grid(NBATCH, HID / 128); // 512 CTAs, 128 threads
    dim3 mt_grid(HID / 32, (T_STEPS + 31) / 32, 3);

    maskT_kernel<<<mt_grid, dim3(32, 32)>>>(mask1, mask2, mask3);
    split_kernel<<<(HID*HID + 255)/256, 256>>>(W2, W3);
    layer1_kernel<<<rec_grid, 128>>>(x, W1, b1, fr1);
    gemm_bf16<<<gemm_grid, 256, GEMM_SMEM>>>(0);
    layerR_kernel<<<rec_grid, 128>>>(b2, fr2, 1, 2);
    gemm_bf16<<<gemm_grid, 256, GEMM_SMEM>>>(1);
    layerR_kernel<<<rec_grid, 128>>>(b3, fr3, 2, 3);
    head_kernel<<<NBATCH, 320>>>(fr3, W4, b4, outputs);
    lfr_kernel<<<3, 256>>>(fr1, lfr);
}